// round 11
// baseline (speedup 1.0000x reference)
#include <cuda_runtime.h>

// SPD log-map: for each 64x64 SPD matrix A, compute logm(A) = U diag(log w) U^T
// and emit the row-major upper triangle (2080 floats).
//
// One-sided Jacobi on B := A; at convergence columns are orthogonal with
// norms = eigenvalues, and logm(A) = B diag(log(l)/l^2) B^T.
//
// R11: register-resident systolic columns. Each 16-lane half-warp holds its
// (p, q) column pair in registers (4 floats per column per lane). Round-robin
// column flow is p_w <- p_{w+1}, q_w <- q_{w-1} (p31 <- q31, q0 <- p1):
//  - odd->even and even->odd transfers inside a warp use shfl_xor(16)
//  - cross-warp transfers use Bs as a mailbox (store at the column's own
//    index pre-barrier; receiver loads at its incremented index post-barrier)
//  - the apq dot reads registers (no LDS on the critical path)
// One __syncthreads per round; sweep-phase smem traffic is ~halved vs R9.

#define MDIM 64
#define LD2  33          // float2 stride per column (odd -> conflict-free)
#define LDF  66
#define MAXSWEEP 24
#define NTRI 2080
#define RTOL 1e-13f      // rotate above ~3e-7 relative orthogonality
#define QTOL 1e-8f       // sweep "significant" above ~1e-4 relative

__device__ __forceinline__ float half_sum(float v) {
    #pragma unroll
    for (int o = 8; o; o >>= 1)
        v += __shfl_xor_sync(0xffffffffu, v, o);
    return v;                 // sum within each 16-lane half-warp
}

__global__ __launch_bounds__(512, 4)
void spd_log_kernel(const float* __restrict__ in, float* __restrict__ out)
{
    __shared__ float2 Bs[MDIM * LD2];   // column c: float2 j = rows (2j,2j+1)
    __shared__ float  cn[MDIM];
    __shared__ float  dv[MDIM];
    __shared__ int    nsig;

    const int tid    = threadIdx.x;
    const int pairid = tid >> 4;        // 0..31: half-warp (group) id
    const int hl     = tid & 15;        // lane within group
    const int warp   = tid >> 5;        // 0..15
    const int lane   = tid & 31;

    float* Bf = (float*)Bs;             // B[r, c] == Bf[c*LDF + r]

    const float* A = in  + (size_t)blockIdx.x * (MDIM * MDIM);
    float*       O = out + (size_t)blockIdx.x * NTRI;

    // Load (A symmetric): Bf[c*LDF + r] = A[c*64 + r]; contiguous both sides.
    for (int e = tid; e < MDIM * MDIM; e += 512) {
        int c = e >> 6, r = e & 63;
        Bf[c * LDF + r] = A[e];
    }
    if (tid == 0) nsig = 0;
    __syncthreads();

    // ---- Load column pair into registers ----
    int pidx = (pairid == 0) ? 63 : pairid;
    int qidx = (pairid == 0) ? 0  : 63 - pairid;

    float2 P0 = Bs[pidx * LD2 + hl], P1 = Bs[pidx * LD2 + 16 + hl];
    float2 Q0 = Bs[qidx * LD2 + hl], Q1 = Bs[qidx * LD2 + 16 + hl];

    const bool evenHalf = (lane < 16);
    const bool w0    = (warp == 0);
    const bool wLast = (warp == 15);

    // ---- One-sided Jacobi sweeps (adaptive) ----
    for (int sw = 0; sw < MAXSWEEP; sw++) {
        // Exact column norms from registers.
        float np = half_sum(fmaf(P0.x, P0.x, P0.y * P0.y) +
                            fmaf(P1.x, P1.x, P1.y * P1.y));
        float nq = half_sum(fmaf(Q0.x, Q0.x, Q0.y * Q0.y) +
                            fmaf(Q1.x, Q1.x, Q1.y * Q1.y));
        if (hl == 0) { cn[pidx] = np; cn[qidx] = nq; }
        __syncthreads();

        for (int rr = 0; rr < 63; rr++) {
            float app = cn[pidx], aqq = cn[qidx];

            float apq = half_sum(fmaf(P0.x, Q0.x, P0.y * Q0.y) +
                                 fmaf(P1.x, Q1.x, P1.y * Q1.y));

            float a2 = apq * apq, pr = app * aqq;
            bool rot = a2 > RTOL * pr;              // uniform per group
            if (__any_sync(0xffffffffu, rot)) {
                float th = (aqq - app) / (2.0f * apq);
                float t  = copysignf(1.0f, th) / (fabsf(th) + sqrtf(1.0f + th * th));
                float c  = rsqrtf(1.0f + t * t);
                float s  = t * c;
                if (rot) {
                    float2 nP0 = make_float2(c * P0.x - s * Q0.x, c * P0.y - s * Q0.y);
                    float2 nP1 = make_float2(c * P1.x - s * Q1.x, c * P1.y - s * Q1.y);
                    float2 nQ0 = make_float2(s * P0.x + c * Q0.x, s * P0.y + c * Q0.y);
                    float2 nQ1 = make_float2(s * P1.x + c * Q1.x, s * P1.y + c * Q1.y);
                    P0 = nP0; P1 = nP1; Q0 = nQ0; Q1 = nQ1;
                    if (hl == 0) {
                        cn[pidx] = app - t * apq;
                        cn[qidx] = aqq + t * apq;
                        if (a2 > QTOL * pr) nsig = 1;
                    }
                }
            }

            // ---- Systolic exchange ----
            // Mailbox stores (cross-warp transfers): even half sends P to the
            // previous warp's odd group; odd half sends Q to the next warp's
            // even group. Group 0's p is fixed; group 31's q self-swaps.
            {
                bool doStore = evenHalf ? !w0 : !wLast;
                int   sidx = evenHalf ? pidx : qidx;
                float2 s0  = evenHalf ? P0 : Q0;
                float2 s1  = evenHalf ? P1 : Q1;
                if (doStore) {
                    Bs[sidx * LD2 + hl]      = s0;
                    Bs[sidx * LD2 + 16 + hl] = s1;
                }
            }
            __syncthreads();

            // Intra-warp transfers via shfl_xor(16): lanes 0-15 see odd
            // half's P; lanes 16-31 see even half's Q.
            float tpx0 = __shfl_xor_sync(0xffffffffu, P0.x, 16);
            float tpy0 = __shfl_xor_sync(0xffffffffu, P0.y, 16);
            float tpx1 = __shfl_xor_sync(0xffffffffu, P1.x, 16);
            float tpy1 = __shfl_xor_sync(0xffffffffu, P1.y, 16);
            float tqx0 = __shfl_xor_sync(0xffffffffu, Q0.x, 16);
            float tqy0 = __shfl_xor_sync(0xffffffffu, Q0.y, 16);
            float tqx1 = __shfl_xor_sync(0xffffffffu, Q1.x, 16);
            float tqy1 = __shfl_xor_sync(0xffffffffu, Q1.y, 16);

            // Advance column indices (columns keep their identity).
            if (pairid) { pidx++; if (pidx == 63) pidx = 0; }
            qidx++; if (qidx == 63) qidx = 0;

            if (evenHalf) {
                if (w0) {
                    // q0 <- p1 (intra-warp); p0 stays (column 63 fixed).
                    Q0 = make_float2(tpx0, tpy0); Q1 = make_float2(tpx1, tpy1);
                } else {
                    P0 = make_float2(tpx0, tpy0); P1 = make_float2(tpx1, tpy1);
                    Q0 = Bs[qidx * LD2 + hl];     Q1 = Bs[qidx * LD2 + 16 + hl];
                }
            } else {
                float2 oQ0 = Q0, oQ1 = Q1;
                Q0 = make_float2(tqx0, tqy0); Q1 = make_float2(tqx1, tqy1);
                if (wLast) {           // p31 <- own old q31
                    P0 = oQ0; P1 = oQ1;
                } else {
                    P0 = Bs[pidx * LD2 + hl]; P1 = Bs[pidx * LD2 + 16 + hl];
                }
            }
        }

        int s = nsig;
        __syncthreads();
        if (tid == 0) nsig = 0;
        __syncthreads();
        if (s == 0) break;
    }

    // ---- Write all columns back to smem for dv + reconstruction ----
    Bs[pidx * LD2 + hl]      = P0;  Bs[pidx * LD2 + 16 + hl] = P1;
    Bs[qidx * LD2 + hl]      = Q0;  Bs[qidx * LD2 + 16 + hl] = Q1;
    __syncthreads();

    // ---- dv_k = log(l_k)/l_k^2 = 0.5*log(n2)/n2, n2 = l^2 ----
    #pragma unroll
    for (int h = 0; h < 2; h++) {
        int k = pairid + 32 * h;
        float2 x0 = Bs[k * LD2 + hl];
        float2 x1 = Bs[k * LD2 + 16 + hl];
        float n2 = half_sum(fmaf(x0.x, x0.x, x0.y * x0.y) +
                            fmaf(x1.x, x1.x, x1.y * x1.y));
        if (hl == 0) dv[k] = 0.5f * logf(n2) / n2;
    }
    __syncthreads();

    // ---- out[i][j] = sum_k dv[k]*B[i,k]*B[j,k], i<=j.
    //      Warp w owns rows {w, 63-w, 16+w, 47-w}: 130 elements each. ----
    #pragma unroll
    for (int rsel = 0; rsel < 4; rsel++) {
        int i = (rsel == 0) ? warp
              : (rsel == 1) ? 63 - warp
              : (rsel == 2) ? 16 + warp
                            : 47 - warp;
        int base = i * (129 - i) / 2;
        for (int j = i + lane; j < MDIM; j += 32) {
            float acc = 0.0f;
            #pragma unroll
            for (int k = 0; k < MDIM; k++)
                acc += (dv[k] * Bf[k * LDF + i]) * Bf[k * LDF + j];
            O[base + (j - i)] = acc;
        }
    }
}

extern "C" void kernel_launch(void* const* d_in, const int* in_sizes, int n_in,
                              void* d_out, int out_size)
{
    const float* A = (const float*)d_in[0];
    float* out = (float*)d_out;
    int batch = in_sizes[0] / (MDIM * MDIM);   // 8192
    spd_log_kernel<<<batch, 512>>>(A, out);
}

// round 12
// speedup vs baseline: 1.6604x; 1.6604x over previous
#include <cuda_runtime.h>

// SPD log-map: for each 64x64 SPD matrix A, compute logm(A) = U diag(log w) U^T
// and emit the row-major upper triangle (2080 floats).
//
// One-sided Jacobi on B := A; at convergence columns are orthogonal with
// norms = eigenvalues, and logm(A) = B diag(log(l)/l^2) B^T.
// R12 = R9 structure (512 thr, 16-lane half-warp per column pair, smem-resident
// columns, 1 barrier/round) with fewer instructions:
//  - float4 column slices: 2 LDS.128 + 2 STS.128 per round (LDF=68 keeps every
//    column 16B-aligned and LDS.128 phases conflict-free)
//  - packed f32x2 mul/fma for dots, rotations, and reconstruction
//  - MUFU-based div/sqrt for the rotation scalars (no IEEE subroutines)

#define MDIM 64
#define LDF  68          // floats per column slot
#define LD2  34          // float2 stride
#define LD4  17          // float4 stride
#define MAXSWEEP 24
#define NTRI 2080
#define RTOL 1e-13f      // rotate above ~3e-7 relative orthogonality
#define QTOL 1e-8f       // sweep "significant" above ~1e-4 relative

typedef unsigned long long u64;

__device__ __forceinline__ u64 pk2(float x, float y) {
    u64 r; asm("mov.b64 %0, {%1, %2};" : "=l"(r) : "f"(x), "f"(y)); return r;
}
__device__ __forceinline__ float2 upk(u64 v) {
    float lo, hi; asm("mov.b64 {%0, %1}, %2;" : "=f"(lo), "=f"(hi) : "l"(v));
    return make_float2(lo, hi);
}
__device__ __forceinline__ u64 mul2(u64 a, u64 b) {
    u64 r; asm("mul.rn.f32x2 %0, %1, %2;" : "=l"(r) : "l"(a), "l"(b)); return r;
}
__device__ __forceinline__ u64 fma2(u64 a, u64 b, u64 c) {
    u64 r; asm("fma.rn.f32x2 %0, %1, %2, %3;" : "=l"(r) : "l"(a), "l"(b), "l"(c));
    return r;
}

__device__ __forceinline__ float half_sum(float v) {
    #pragma unroll
    for (int o = 8; o; o >>= 1)
        v += __shfl_xor_sync(0xffffffffu, v, o);
    return v;                 // sum within each 16-lane half-warp
}

__global__ __launch_bounds__(512, 4)
void spd_log_kernel(const float* __restrict__ in, float* __restrict__ out)
{
    __shared__ float4 Bs4[MDIM * LD4];  // column c: float4 g = rows 4g..4g+3
    __shared__ float  cn[MDIM];
    __shared__ float  dv[MDIM];
    __shared__ int    nsig;

    const int tid    = threadIdx.x;
    const int pairid = tid >> 4;        // 0..31: half-warp (group) id
    const int hl     = tid & 15;        // lane within group
    const int warp   = tid >> 5;        // 0..15
    const int lane   = tid & 31;

    float* Bf = (float*)Bs4;            // B[r, c] == Bf[c*LDF + r]

    const float* A = in  + (size_t)blockIdx.x * (MDIM * MDIM);
    float*       O = out + (size_t)blockIdx.x * NTRI;

    // Load (A symmetric): Bf[c*LDF + r] = A[c*64 + r]; contiguous both sides.
    for (int e = tid; e < MDIM * MDIM; e += 512) {
        int c = e >> 6, r = e & 63;
        Bf[c * LDF + r] = A[e];
    }
    if (tid == 0) nsig = 0;
    __syncthreads();

    // ---- One-sided Jacobi sweeps (adaptive) ----
    for (int sw = 0; sw < MAXSWEEP; sw++) {
        // Exact norms of this group's own two columns.
        int p0 = (pairid == 0) ? 63 : pairid;
        int q0 = (pairid == 0) ? 0  : 63 - pairid;
        {
            float4 XP = Bs4[p0 * LD4 + hl];
            float4 XQ = Bs4[q0 * LD4 + hl];
            u64 pa = pk2(XP.x, XP.y), pb = pk2(XP.z, XP.w);
            u64 qa = pk2(XQ.x, XQ.y), qb = pk2(XQ.z, XQ.w);
            float2 fp = upk(fma2(pb, pb, mul2(pa, pa)));
            float2 fq = upk(fma2(qb, qb, mul2(qa, qa)));
            float np = half_sum(fp.x + fp.y);
            float nq = half_sum(fq.x + fq.y);
            if (hl == 0) { cn[p0] = np; cn[q0] = nq; }
        }
        __syncthreads();

        int p = p0, q = q0;
        for (int rr = 0; rr < 63; rr++) {
            float4 P = Bs4[p * LD4 + hl];
            float4 Q = Bs4[q * LD4 + hl];
            float app = cn[p], aqq = cn[q];

            u64 pxy = pk2(P.x, P.y), pzw = pk2(P.z, P.w);
            u64 qxy = pk2(Q.x, Q.y), qzw = pk2(Q.z, Q.w);

            float2 df = upk(fma2(pzw, qzw, mul2(pxy, qxy)));
            float apq = half_sum(df.x + df.y);

            float a2 = apq * apq, pr = app * aqq;
            bool rot = a2 > RTOL * pr;              // uniform per group
            if (__any_sync(0xffffffffu, rot)) {
                // Rotation scalars via MUFU (approx err ~2^-22; self-corrected).
                float th  = __fdividef(aqq - app, 2.0f * apq);
                float h2  = fmaf(th, th, 1.0f);
                float hyp = h2 * rsqrtf(h2);                 // sqrt(1+th^2)
                float t   = copysignf(__fdividef(1.0f, fabsf(th) + hyp), th);
                float c   = rsqrtf(fmaf(t, t, 1.0f));
                float s   = t * c;

                if (rot) {
                    u64 cc = pk2(c, c), ss = pk2(s, s), ns = pk2(-s, -s);
                    float2 a0 = upk(fma2(cc, pxy, mul2(ns, qxy)));
                    float2 a1 = upk(fma2(cc, pzw, mul2(ns, qzw)));
                    float2 b0 = upk(fma2(cc, qxy, mul2(ss, pxy)));
                    float2 b1 = upk(fma2(cc, qzw, mul2(ss, pzw)));
                    Bs4[p * LD4 + hl] = make_float4(a0.x, a0.y, a1.x, a1.y);
                    Bs4[q * LD4 + hl] = make_float4(b0.x, b0.y, b1.x, b1.y);
                    if (hl == 0) {
                        cn[p] = app - t * apq;
                        cn[q] = aqq + t * apq;
                        if (a2 > QTOL * pr) nsig = 1;
                    }
                }
            }
            __syncthreads();

            if (pairid) { p++; if (p == 63) p = 0; }
            q++; if (q == 63) q = 0;
        }

        int sdone = nsig;
        __syncthreads();
        if (tid == 0) nsig = 0;
        __syncthreads();
        if (sdone == 0) break;
    }

    // ---- dv_k = log(l_k)/l_k^2 = 0.5*log(n2)/n2, n2 = l^2 ----
    #pragma unroll
    for (int h = 0; h < 2; h++) {
        int k = pairid + 32 * h;
        float4 X = Bs4[k * LD4 + hl];
        u64 xa = pk2(X.x, X.y), xb = pk2(X.z, X.w);
        float2 f = upk(fma2(xb, xb, mul2(xa, xa)));
        float n2 = half_sum(f.x + f.y);
        if (hl == 0) dv[k] = 0.5f * logf(n2) / n2;
    }
    __syncthreads();

    // ---- out[i][j] = sum_k dv[k]*B[i,k]*B[j,k], i<=j.
    //      Warp w owns rows {w, 63-w, 16+w, 47-w}. Each lane covers a j-pair
    //      (j0, j0+1) with a float2 load + packed FMA. ----
    #pragma unroll
    for (int rsel = 0; rsel < 4; rsel++) {
        int i = (rsel == 0) ? warp
              : (rsel == 1) ? 63 - warp
              : (rsel == 2) ? 16 + warp
                            : 47 - warp;
        int base = i * (129 - i) / 2;
        int je = i & ~1;                 // even start so float2 loads align
        int j0 = je + 2 * lane;
        if (j0 < MDIM) {
            u64 acc = 0;                 // packed (0.0f, 0.0f)
            #pragma unroll
            for (int k = 0; k < MDIM; k++) {
                float ci = dv[k] * Bf[k * LDF + i];
                const float2 bj = *(const float2*)(Bf + k * LDF + j0);
                acc = fma2(pk2(ci, ci), pk2(bj.x, bj.y), acc);
            }
            float2 r = upk(acc);
            if (j0 >= i)     O[base + (j0 - i)]     = r.x;
            /* j0+1 > i always here */ O[base + (j0 + 1 - i)] = r.y;
        }
    }
}

extern "C" void kernel_launch(void* const* d_in, const int* in_sizes, int n_in,
                              void* d_out, int out_size)
{
    const float* A = (const float*)d_in[0];
    float* out = (float*)d_out;
    int batch = in_sizes[0] / (MDIM * MDIM);   // 8192
    spd_log_kernel<<<batch, 512>>>(A, out);
}